// round 10
// baseline (speedup 1.0000x reference)
#include <cuda_runtime.h>
#include <cuda_bf16.h>

// C=16, E=64, N=256. Fully fused:
//   O[ce,i] = sum_j v[ce,j]*exp(q[ce,i]*k[ce,j]/8) / sum_j exp(...)
//   Y = reshape(O,(4096,64)) @ W^T + b    (GEMM row = 64 tokens of a channel)
//
// Taylor-moment attention (m=0..9), packed f32x2 in phase 1.
// Warp-specialized: warps 0-7 compute channel moments+Horner; warps 8-15
// stage W row-major (float4, conflict-free). One barrier, then all 16 warps
// split the projection: warp w -> feats 4w..4w+3, lane -> block row.
// O smem uses pad-65 (stride 65 -> bank (lane+idx)%32, conflict-free) and is
// therefore written with SCALAR stores (65*row offset breaks 16B alignment).

#define NTERMS 10

__device__ __constant__ float c_invfact[NTERMS] = {
    1.0f, 1.0f, 0.5f,
    1.6666667e-1f, 4.1666667e-2f, 8.3333333e-3f,
    1.3888889e-3f, 1.9841270e-4f, 2.4801587e-5f,
    2.7557319e-6f
};

typedef unsigned long long u64;

__device__ __forceinline__ u64 pack2(float lo, float hi) {
    u64 r; asm("mov.b64 %0, {%1, %2};" : "=l"(r) : "f"(lo), "f"(hi)); return r;
}
__device__ __forceinline__ void unpack2(u64 v, float& lo, float& hi) {
    asm("mov.b64 {%0, %1}, %2;" : "=f"(lo), "=f"(hi) : "l"(v));
}
__device__ __forceinline__ u64 ffma2(u64 a, u64 b, u64 c) {
    u64 d; asm("fma.rn.f32x2 %0, %1, %2, %3;" : "=l"(d) : "l"(a), "l"(b), "l"(c));
    return d;
}
__device__ __forceinline__ u64 fmul2(u64 a, u64 b) {
    u64 d; asm("mul.rn.f32x2 %0, %1, %2;" : "=l"(d) : "l"(a), "l"(b));
    return d;
}
__device__ __forceinline__ u64 fadd2(u64 a, u64 b) {
    u64 d; asm("add.rn.f32x2 %0, %1, %2;" : "=l"(d) : "l"(a), "l"(b));
    return d;
}

// ---------------------------------------------------------------------------
// 128 blocks x 512 threads (16 warps).
// ---------------------------------------------------------------------------
__global__ void __launch_bounds__(512)
ca_fused_kernel(const float* __restrict__ q,
                const float* __restrict__ k,
                const float* __restrict__ v,
                const float* __restrict__ W,
                const float* __restrict__ bias,
                float* __restrict__ Y)
{
    __shared__ float Wsh[64 * 64];   // row-major: Wsh[f*64 + kk]
    __shared__ float Osh[32 * 65];   // block rows of O, pad 65

    const int t    = threadIdx.x;
    const int wid  = t >> 5;         // 0..15
    const int lane = t & 31;

    // phase-2 bias (warp-uniform, 16B aligned: wid*4 floats = 16*wid bytes)
    const float4 bias4 = *(const float4*)(bias + wid * 4);

    if (wid < 8) {
        // ================= Phase 1: attention for channel ce ==============
        const int ce = blockIdx.x * 8 + wid;
        const float4* kp4 = (const float4*)(k + ce * 256) + lane * 2;
        const float4* vp4 = (const float4*)(v + ce * 256) + lane * 2;
        const float4* qp4 = (const float4*)(q + ce * 256) + lane * 2;
        float4 kA = kp4[0], kB = kp4[1];
        float4 vA = vp4[0], vB = vp4[1];
        float4 qA = qp4[0], qB = qp4[1];

        u64 b2[8], vv2[8], pw2[8];
        {
            float bb[8] = {kA.x, kA.y, kA.z, kA.w, kB.x, kB.y, kB.z, kB.w};
            float vv[8] = {vA.x, vA.y, vA.z, vA.w, vB.x, vB.y, vB.z, vB.w};
#pragma unroll
            for (int u = 0; u < 8; u++) {
                float bu = bb[u] * 0.125f;
                b2[u]  = pack2(bu, bu);
                vv2[u] = pack2(1.0f, vv[u]);
                pw2[u] = pack2(1.0f, 1.0f);
            }
        }

        u64 M[NTERMS];   // packed {S_m, Mv_m} per-lane partials
#pragma unroll
        for (int m = 0; m < NTERMS; m++) {
            u64 acc = 0ull;
#pragma unroll
            for (int u = 0; u < 8; u++) {
                acc    = ffma2(vv2[u], pw2[u], acc);
                pw2[u] = fmul2(pw2[u], b2[u]);
            }
            M[m] = acc;
        }

        // packed butterfly
#pragma unroll
        for (int off = 16; off; off >>= 1) {
#pragma unroll
            for (int m = 0; m < NTERMS; m++)
                M[m] = fadd2(M[m], __shfl_xor_sync(0xffffffffu, M[m], off));
        }

        // fold 1/m!
#pragma unroll
        for (int m = 0; m < NTERMS; m++) {
            float f = c_invfact[m];
            M[m] = fmul2(M[m], pack2(f, f));
        }

        // Horner per query -> O into smem (SCALAR stores; pad-65 layout)
        {
            float a[8] = {qA.x, qA.y, qA.z, qA.w, qB.x, qB.y, qB.z, qB.w};
            float* od = &Osh[(wid * 4 + (lane >> 3)) * 65 + (lane & 7) * 8];
#pragma unroll
            for (int u = 0; u < 8; u++) {
                u64 a2 = pack2(a[u], a[u]);
                u64 h = M[NTERMS - 1];
#pragma unroll
                for (int m = NTERMS - 2; m >= 0; m--)
                    h = ffma2(h, a2, M[m]);
                float den, num;
                unpack2(h, den, num);
                od[u] = __fdividef(num, den);
            }
        }
    } else {
        // ================= W staging warps (8-15) =========================
        const int t2 = t - 256;          // 0..255
#pragma unroll
        for (int i = 0; i < 4; i++) {
            int idx = t2 + 256 * i;
            ((float4*)Wsh)[idx] = ((const float4*)W)[idx];
        }
    }

    __syncthreads();

    // ============ Phase 2: projection (all 16 warps) ======================
    // warp wid -> feats f0 = wid*4 .. +3; lane -> block row.
    const int f0 = wid * 4;
    const float* orow = &Osh[lane * 65];
    const float* wrow = &Wsh[f0 * 64];

    float acc0 = bias4.x, acc1 = bias4.y, acc2 = bias4.z, acc3 = bias4.w;

#pragma unroll
    for (int c = 0; c < 16; c++) {
        float o0 = orow[4 * c + 0];
        float o1 = orow[4 * c + 1];
        float o2 = orow[4 * c + 2];
        float o3 = orow[4 * c + 3];
        float4 w0 = *(const float4*)&wrow[0 * 64 + 4 * c];   // broadcast
        float4 w1 = *(const float4*)&wrow[1 * 64 + 4 * c];
        float4 w2 = *(const float4*)&wrow[2 * 64 + 4 * c];
        float4 w3 = *(const float4*)&wrow[3 * 64 + 4 * c];
        acc0 = fmaf(o0, w0.x, acc0); acc0 = fmaf(o1, w0.y, acc0);
        acc0 = fmaf(o2, w0.z, acc0); acc0 = fmaf(o3, w0.w, acc0);
        acc1 = fmaf(o0, w1.x, acc1); acc1 = fmaf(o1, w1.y, acc1);
        acc1 = fmaf(o2, w1.z, acc1); acc1 = fmaf(o3, w1.w, acc1);
        acc2 = fmaf(o0, w2.x, acc2); acc2 = fmaf(o1, w2.y, acc2);
        acc2 = fmaf(o2, w2.z, acc2); acc2 = fmaf(o3, w2.w, acc2);
        acc3 = fmaf(o0, w3.x, acc3); acc3 = fmaf(o1, w3.y, acc3);
        acc3 = fmaf(o2, w3.z, acc3); acc3 = fmaf(o3, w3.w, acc3);
    }

    // write Y[blockRow][f0..f0+3]
    {
        float* yp = &Y[(blockIdx.x * 32 + lane) * 64 + f0];
        *(float4*)yp = make_float4(acc0, acc1, acc2, acc3);
    }
}

// ---------------------------------------------------------------------------
extern "C" void kernel_launch(void* const* d_in, const int* in_sizes, int n_in,
                              void* d_out, int out_size)
{
    const float* q  = (const float*)d_in[0];
    const float* k  = (const float*)d_in[1];
    const float* v  = (const float*)d_in[2];
    const float* W  = (const float*)d_in[3];
    const float* b  = (const float*)d_in[4];
    float* out = (float*)d_out;

    ca_fused_kernel<<<128, 512>>>(q, k, v, W, b, out);
    (void)in_sizes; (void)n_in; (void)out_size;
}

// round 11
// speedup vs baseline: 1.0037x; 1.0037x over previous
#include <cuda_runtime.h>
#include <cuda_bf16.h>

// C=16, E=64, N=256. Fully fused:
//   O[ce,i] = sum_j v[ce,j]*exp(q[ce,i]*k[ce,j]/8) / sum_j exp(...)
//   Y = reshape(O,(4096,64)) @ W^T + b    (GEMM row = 64 tokens of a channel)
//
// Taylor-moment attention (m=0..8), packed f32x2 in phase 1.
// Warp-specialized: warps 0-7 compute channel moments+Horner; warps 8-15
// stage W row-major (float4 copy, no transpose). One barrier; then all 16
// warps run the projection with PACKED k-pair accumulators:
//   acc_f(u64) += {o_2c, o_2c+1} * {W[f][2c], W[f][2c+1]}   (FFMA2)
// horizontal-added once at the end. O pairs come free from the float4 row
// load; W pairs from broadcast ulonglong2 loads of row-major Wsh.

#define NTERMS 9

__device__ __constant__ float c_invfact[NTERMS] = {
    1.0f, 1.0f, 0.5f,
    1.6666667e-1f, 4.1666667e-2f, 8.3333333e-3f,
    1.3888889e-3f, 1.9841270e-4f, 2.4801587e-5f
};

typedef unsigned long long u64;

__device__ __forceinline__ u64 pack2(float lo, float hi) {
    u64 r; asm("mov.b64 %0, {%1, %2};" : "=l"(r) : "f"(lo), "f"(hi)); return r;
}
__device__ __forceinline__ void unpack2(u64 v, float& lo, float& hi) {
    asm("mov.b64 {%0, %1}, %2;" : "=f"(lo), "=f"(hi) : "l"(v));
}
__device__ __forceinline__ u64 ffma2(u64 a, u64 b, u64 c) {
    u64 d; asm("fma.rn.f32x2 %0, %1, %2, %3;" : "=l"(d) : "l"(a), "l"(b), "l"(c));
    return d;
}
__device__ __forceinline__ u64 fmul2(u64 a, u64 b) {
    u64 d; asm("mul.rn.f32x2 %0, %1, %2;" : "=l"(d) : "l"(a), "l"(b));
    return d;
}
__device__ __forceinline__ u64 fadd2(u64 a, u64 b) {
    u64 d; asm("add.rn.f32x2 %0, %1, %2;" : "=l"(d) : "l"(a), "l"(b));
    return d;
}

// ---------------------------------------------------------------------------
// 128 blocks x 512 threads (16 warps).
// Phase 1: warp w<8 -> channel ce = 8*bid + w; warps 8-15 stage W.
// Phase 2: warp w -> features 4w..4w+3, lane -> block row 0..31.
// ---------------------------------------------------------------------------
__global__ void __launch_bounds__(512)
ca_fused_kernel(const float* __restrict__ q,
                const float* __restrict__ k,
                const float* __restrict__ v,
                const float* __restrict__ W,
                const float* __restrict__ bias,
                float* __restrict__ Y)
{
    __shared__ float Wsh[64 * 64];   // row-major: Wsh[f*64 + kk]
    __shared__ float Osh[32 * 68];   // block rows of O; stride 68 (16B-aligned)

    const int t    = threadIdx.x;
    const int wid  = t >> 5;         // 0..15
    const int lane = t & 31;

    // phase-2 bias (warp-uniform, 16B aligned)
    const float4 bias4 = *(const float4*)(bias + wid * 4);

    if (wid < 8) {
        // ================= Phase 1: attention for channel ce ==============
        const int ce = blockIdx.x * 8 + wid;
        const float4* kp4 = (const float4*)(k + ce * 256) + lane * 2;
        const float4* vp4 = (const float4*)(v + ce * 256) + lane * 2;
        const float4* qp4 = (const float4*)(q + ce * 256) + lane * 2;
        float4 kA = kp4[0], kB = kp4[1];
        float4 vA = vp4[0], vB = vp4[1];
        float4 qA = qp4[0], qB = qp4[1];

        u64 b2[8], vv2[8], pw2[8];
        {
            float bb[8] = {kA.x, kA.y, kA.z, kA.w, kB.x, kB.y, kB.z, kB.w};
            float vv[8] = {vA.x, vA.y, vA.z, vA.w, vB.x, vB.y, vB.z, vB.w};
#pragma unroll
            for (int u = 0; u < 8; u++) {
                float bu = bb[u] * 0.125f;
                b2[u]  = pack2(bu, bu);
                vv2[u] = pack2(1.0f, vv[u]);
                pw2[u] = pack2(1.0f, 1.0f);
            }
        }

        u64 M[NTERMS];   // packed {S_m, Mv_m} per-lane partials
#pragma unroll
        for (int m = 0; m < NTERMS; m++) {
            u64 acc = 0ull;
#pragma unroll
            for (int u = 0; u < 8; u++) {
                acc    = ffma2(vv2[u], pw2[u], acc);
                pw2[u] = fmul2(pw2[u], b2[u]);
            }
            M[m] = acc;
        }

        // packed butterfly
#pragma unroll
        for (int off = 16; off; off >>= 1) {
#pragma unroll
            for (int m = 0; m < NTERMS; m++)
                M[m] = fadd2(M[m], __shfl_xor_sync(0xffffffffu, M[m], off));
        }

        // fold 1/m!
#pragma unroll
        for (int m = 0; m < NTERMS; m++) {
            float f = c_invfact[m];
            M[m] = fmul2(M[m], pack2(f, f));
        }

        // Horner per query -> O into smem (scalar stores; stride-68 layout)
        {
            float a[8] = {qA.x, qA.y, qA.z, qA.w, qB.x, qB.y, qB.z, qB.w};
            float* od = &Osh[(wid * 4 + (lane >> 3)) * 68 + (lane & 7) * 8];
#pragma unroll
            for (int u = 0; u < 8; u++) {
                u64 a2 = pack2(a[u], a[u]);
                u64 h = M[NTERMS - 1];
#pragma unroll
                for (int m = NTERMS - 2; m >= 0; m--)
                    h = ffma2(h, a2, M[m]);
                float den, num;
                unpack2(h, den, num);
                od[u] = __fdividef(num, den);
            }
        }
    } else {
        // ================= W staging warps (8-15) =========================
        const int t2 = t - 256;          // 0..255
#pragma unroll
        for (int i = 0; i < 4; i++) {
            int idx = t2 + 256 * i;
            ((float4*)Wsh)[idx] = ((const float4*)W)[idx];
        }
    }

    __syncthreads();

    // ============ Phase 2: projection (all 16 warps, packed k-pairs) ======
    // warp wid -> feats f0 = wid*4 .. +3; lane -> block row.
    // Accumulators: u64 {sum over even k, sum over odd k} per feature.
    const int f0 = wid * 4;
    const float4* orow4 = (const float4*)&Osh[lane * 68];   // 68 = 17 float4
    const float* wrow = &Wsh[f0 * 64];

    u64 acc0 = pack2(bias4.x, 0.0f);
    u64 acc1 = pack2(bias4.y, 0.0f);
    u64 acc2 = pack2(bias4.z, 0.0f);
    u64 acc3 = pack2(bias4.w, 0.0f);

#pragma unroll
    for (int c = 0; c < 16; c++) {
        float4 o4 = orow4[c];                       // o[4c..4c+3], LDS.128
        u64 op01 = pack2(o4.x, o4.y);               // {o_ev, o_od}
        u64 op23 = pack2(o4.z, o4.w);
        ulonglong2 w0 = *(const ulonglong2*)&wrow[0 * 64 + 4 * c];  // broadcast
        ulonglong2 w1 = *(const ulonglong2*)&wrow[1 * 64 + 4 * c];
        ulonglong2 w2 = *(const ulonglong2*)&wrow[2 * 64 + 4 * c];
        ulonglong2 w3 = *(const ulonglong2*)&wrow[3 * 64 + 4 * c];
        acc0 = ffma2(op01, w0.x, acc0);
        acc1 = ffma2(op01, w1.x, acc1);
        acc2 = ffma2(op01, w2.x, acc2);
        acc3 = ffma2(op01, w3.x, acc3);
        acc0 = ffma2(op23, w0.y, acc0);
        acc1 = ffma2(op23, w1.y, acc1);
        acc2 = ffma2(op23, w2.y, acc2);
        acc3 = ffma2(op23, w3.y, acc3);
    }

    // horizontal add even+odd partials, write Y[blockRow][f0..f0+3]
    {
        float e0, d0, e1, d1, e2, d2, e3, d3;
        unpack2(acc0, e0, d0);
        unpack2(acc1, e1, d1);
        unpack2(acc2, e2, d2);
        unpack2(acc3, e3, d3);
        float* yp = &Y[(blockIdx.x * 32 + lane) * 64 + f0];
        *(float4*)yp = make_float4(e0 + d0, e1 + d1, e2 + d2, e3 + d3);
    }
}

// ---------------------------------------------------------------------------
extern "C" void kernel_launch(void* const* d_in, const int* in_sizes, int n_in,
                              void* d_out, int out_size)
{
    const float* q  = (const float*)d_in[0];
    const float* k  = (const float*)d_in[1];
    const float* v  = (const float*)d_in[2];
    const float* W  = (const float*)d_in[3];
    const float* b  = (const float*)d_in[4];
    float* out = (float*)d_out;

    ca_fused_kernel<<<128, 512>>>(q, k, v, W, b, out);
    (void)in_sizes; (void)n_in; (void)out_size;
}